// round 7
// baseline (speedup 1.0000x reference)
#include <cuda_runtime.h>

// FilterLayer: y[b,c,h,w] = sum_{i,j in 5x5} x_pad[b,c,h+i,w+j] * f[b,i*5+j,h,w]
// x [4,3,512,512] f32, f [4,25,512,512] f32, out [4,3,512,512] f32.

#define Hc 512
#define Wc 512
#define Bc 4
#define Cc 3
#define WIN 5
#define NK (WIN * WIN)
#define PAD (WIN / 2)

#define TILE_W 128            // 32 threads x 4 px
#define TILE_H 8
#define TW (TILE_W + 2 * PAD) // 132 floats per row (rows stay 16B aligned)
#define TH (TILE_H + 2 * PAD) // 12

__global__ __launch_bounds__(256, 3)
void filter5x5_kernel(const float* __restrict__ x,
                      const float* __restrict__ f,
                      float* __restrict__ out)
{
    __shared__ float xs[Cc][TH][TW]; // 19008 B

    const int tx  = threadIdx.x;      // 0..31
    const int ty  = threadIdx.y;      // 0..7
    const int tid = ty * 32 + tx;
    const int b   = blockIdx.z;
    const int h0  = blockIdx.y * TILE_H;
    const int w0  = blockIdx.x * TILE_W;

    // ---- cooperative x halo load (3 x 12 x 132) ----
    #pragma unroll 1
    for (int idx = tid; idx < Cc * TH * TW; idx += 256) {
        const int c   = idx / (TH * TW);
        const int rem = idx - c * (TH * TW);
        const int r   = rem / TW;
        const int cc  = rem - r * TW;
        const int gh  = h0 + r - PAD;
        const int gw  = w0 + cc - PAD;
        float v = 0.0f;
        if (gh >= 0 && gh < Hc && gw >= 0 && gw < Wc)
            v = x[((b * Cc + c) * Hc + gh) * Wc + gw];
        xs[c][r][cc] = v;
    }
    __syncthreads();

    float acc[Cc][4];
    #pragma unroll
    for (int c = 0; c < Cc; c++)
        #pragma unroll
        for (int p = 0; p < 4; p++)
            acc[c][p] = 0.0f;

    const int h = h0 + ty;
    const int w = w0 + tx * 4;

    const float4* f4 = reinterpret_cast<const float4*>(
        f + ((b * NK) * Hc + h) * Wc + w);
    const int kstride4 = (Hc * Wc) / 4;

    // ---- 2-stage software pipeline over the 5 tap rows ----
    // While computing with row i's filters, row i+1's 5 LDG.128s are in flight.
    float4 fk[WIN];
    #pragma unroll
    for (int j = 0; j < WIN; j++)
        fk[j] = f4[j * kstride4];

    #pragma unroll
    for (int i = 0; i < WIN; i++) {
        float4 fn[WIN];
        if (i < WIN - 1) {
            #pragma unroll
            for (int j = 0; j < WIN; j++)
                fn[j] = f4[((i + 1) * WIN + j) * kstride4];
        }

        // Channels sequential: only 8 x-values live at a time.
        #pragma unroll
        for (int c = 0; c < Cc; c++) {
            const float4* row = reinterpret_cast<const float4*>(&xs[c][ty + i][0]);
            const float4 a  = row[tx];
            const float4 bq = row[tx + 1];
            float xr[8];
            xr[0] = a.x;  xr[1] = a.y;  xr[2] = a.z;  xr[3] = a.w;
            xr[4] = bq.x; xr[5] = bq.y; xr[6] = bq.z; xr[7] = bq.w;

            #pragma unroll
            for (int j = 0; j < WIN; j++) {
                acc[c][0] = fmaf(fk[j].x, xr[j + 0], acc[c][0]);
                acc[c][1] = fmaf(fk[j].y, xr[j + 1], acc[c][1]);
                acc[c][2] = fmaf(fk[j].z, xr[j + 2], acc[c][2]);
                acc[c][3] = fmaf(fk[j].w, xr[j + 3], acc[c][3]);
            }
        }

        if (i < WIN - 1) {
            #pragma unroll
            for (int j = 0; j < WIN; j++)
                fk[j] = fn[j];
        }
    }

    #pragma unroll
    for (int c = 0; c < Cc; c++) {
        float4 o = make_float4(acc[c][0], acc[c][1], acc[c][2], acc[c][3]);
        *reinterpret_cast<float4*>(out + ((b * Cc + c) * Hc + h) * Wc + w) = o;
    }
}

extern "C" void kernel_launch(void* const* d_in, const int* in_sizes, int n_in,
                              void* d_out, int out_size)
{
    const float* x = (const float*)d_in[0];
    const float* f = (const float*)d_in[1];
    float* out = (float*)d_out;
    (void)in_sizes; (void)n_in; (void)out_size;

    dim3 block(32, 8, 1);
    dim3 grid(Wc / TILE_W, Hc / TILE_H, Bc); // (4, 64, 4)
    filter5x5_kernel<<<grid, block>>>(x, f, out);
}

// round 8
// speedup vs baseline: 1.4677x; 1.4677x over previous
#include <cuda_runtime.h>

// FilterLayer: y[b,c,h,w] = sum_{i,j in 5x5} x_pad[b,c,h+i,w+j] * f[b,i*5+j,h,w]
// x [4,3,512,512] f32, f [4,25,512,512] f32, out [4,3,512,512] f32.
//
// Strategy: f (104.9 MB, zero reuse) is the traffic; stream it via cp.async
// (LDGSTS) into smem so load latency is decoupled from register pressure.

#define Hc 512
#define Wc 512
#define Bc 4
#define Cc 3
#define WIN 5
#define NK (WIN * WIN)
#define PAD (WIN / 2)

#define TILE_W 128
#define TILE_H 4
#define TW (TILE_W + 2 * PAD)   // 132
#define TH (TILE_H + 2 * PAD)   // 8

#define F_FLOATS (NK * TILE_H * TILE_W)   // 12800 floats = 51200 B
#define X_FLOATS (Cc * TH * TW)           // 3168  floats = 12672 B
#define SMEM_BYTES ((F_FLOATS + X_FLOATS) * 4)  // 63872 B

__device__ __forceinline__ void cp_async16(void* smem_dst, const void* gmem_src) {
    unsigned saddr = (unsigned)__cvta_generic_to_shared(smem_dst);
    asm volatile("cp.async.cg.shared.global [%0], [%1], 16;\n"
                 :: "r"(saddr), "l"(gmem_src) : "memory");
}

__global__ __launch_bounds__(256, 3)
void filter5x5_kernel(const float* __restrict__ x,
                      const float* __restrict__ f,
                      float* __restrict__ out)
{
    extern __shared__ float smem[];
    float* fs = smem;              // [25][TILE_H][TILE_W]
    float* xs = smem + F_FLOATS;   // [Cc][TH][TW]

    const int tid = threadIdx.x;   // 0..255
    const int b   = blockIdx.z;
    const int h0  = blockIdx.y * TILE_H;
    const int w0  = blockIdx.x * TILE_W;

    // ---- issue f tile as cp.async (3200 float4s, ~13 per thread, all in flight) ----
    #pragma unroll 1
    for (int idx = tid; idx < F_FLOATS / 4; idx += 256) {
        const int tap  = idx >> 7;          // 128 float4s per tap (4 rows x 32)
        const int rem  = idx & 127;
        const int row  = rem >> 5;
        const int col4 = rem & 31;
        const float* src = f + (((size_t)(b * NK + tap) * Hc + (h0 + row)) * Wc
                                + w0 + col4 * 4);
        cp_async16(fs + (tap * TILE_H + row) * TILE_W + col4 * 4, src);
    }

    // ---- x halo (scalar, mostly L2-resident; overlaps the async f stream) ----
    #pragma unroll
    for (int it = 0; it < (X_FLOATS + 255) / 256; it++) {
        const int idx = tid + it * 256;
        if (idx < X_FLOATS) {
            const int c   = idx / (TH * TW);
            const int rem = idx - c * (TH * TW);
            const int r   = rem / TW;
            const int cc  = rem - r * TW;
            const int gh  = h0 + r - PAD;
            const int gw  = w0 + cc - PAD;
            float v = 0.0f;
            if (gh >= 0 && gh < Hc && gw >= 0 && gw < Wc)
                v = x[((b * Cc + c) * Hc + gh) * Wc + gw];
            xs[idx] = v;
        }
    }

    asm volatile("cp.async.commit_group;\n" ::: "memory");
    asm volatile("cp.async.wait_group 0;\n" ::: "memory");
    __syncthreads();

    // ---- compute: thread -> 2 adjacent pixels, 3 channels ----
    const int tx = tid & 63;   // 0..63 -> w pair
    const int ty = tid >> 6;   // 0..3  -> row
    const int h  = h0 + ty;
    const int w  = w0 + tx * 2;

    float acc[Cc][2];
    #pragma unroll
    for (int c = 0; c < Cc; c++) { acc[c][0] = 0.0f; acc[c][1] = 0.0f; }

    #pragma unroll
    for (int i = 0; i < WIN; i++) {
        // x window per channel: cols [2tx .. 2tx+5] of halo row ty+i -> 3 float2s
        float xr[Cc][6];
        #pragma unroll
        for (int c = 0; c < Cc; c++) {
            const float2* row2 = reinterpret_cast<const float2*>(
                &xs[(c * TH + ty + i) * TW]);
            const float2 q0 = row2[tx];
            const float2 q1 = row2[tx + 1];
            const float2 q2 = row2[tx + 2];
            xr[c][0] = q0.x; xr[c][1] = q0.y;
            xr[c][2] = q1.x; xr[c][3] = q1.y;
            xr[c][4] = q2.x; xr[c][5] = q2.y;
        }
        #pragma unroll
        for (int j = 0; j < WIN; j++) {
            const float2 fk = reinterpret_cast<const float2*>(
                &fs[((i * WIN + j) * TILE_H + ty) * TILE_W])[tx];
            #pragma unroll
            for (int c = 0; c < Cc; c++) {
                acc[c][0] = fmaf(fk.x, xr[c][j + 0], acc[c][0]);
                acc[c][1] = fmaf(fk.y, xr[c][j + 1], acc[c][1]);
            }
        }
    }

    #pragma unroll
    for (int c = 0; c < Cc; c++) {
        float2 o = make_float2(acc[c][0], acc[c][1]);
        *reinterpret_cast<float2*>(out + ((b * Cc + c) * Hc + h) * Wc + w) = o;
    }
}

extern "C" void kernel_launch(void* const* d_in, const int* in_sizes, int n_in,
                              void* d_out, int out_size)
{
    const float* x = (const float*)d_in[0];
    const float* f = (const float*)d_in[1];
    float* out = (float*)d_out;
    (void)in_sizes; (void)n_in; (void)out_size;

    cudaFuncSetAttribute(filter5x5_kernel,
                         cudaFuncAttributeMaxDynamicSharedMemorySize, SMEM_BYTES);

    dim3 block(256, 1, 1);
    dim3 grid(Wc / TILE_W, Hc / TILE_H, Bc); // (4, 128, 4) = 2048 blocks
    filter5x5_kernel<<<grid, block, SMEM_BYTES>>>(x, f, out);
}